// round 5
// baseline (speedup 1.0000x reference)
#include <cuda_runtime.h>
#include <cstdio>

#define NND 20
#define CHN 512
#define HH  64
#define WW  64
#define HW  4096
#define CHW 2097152   // 512*64*64

// Big scratch: [V:1][Gr,Gu,Go:3][cs:1][rh:1][U:1][O:1][h:20][R:20] = 48 planes
__device__ float g_buf[48ll * CHW];
__device__ float g_b[NND * CHN];            // per-node channel bias (lang part + mconv_b)
__device__ float g_t[3 * NND * 9 * CHN];    // per-gate per-node per-tap constant vectors
__device__ int   g_childcount[NND];
__device__ int   g_child[NND * NND];

__device__ __forceinline__ float sigm(float v) { return 1.f / (1.f + expf(-v)); }

// ---------------------------------------------------------------------------
// Tree prep: child lists + counts from adjacency (adj[p*20+c] != 0 => c child of p)
// ---------------------------------------------------------------------------
__global__ void prep_kernel(const int* __restrict__ adj) {
    int n = threadIdx.x;
    if (n < NND) {
        int cnt = 0;
        for (int k = 0; k < NND; k++)
            if (adj[n * NND + k] != 0) g_child[n * NND + cnt++] = k;
        g_childcount[n] = cnt;
    }
}

// ---------------------------------------------------------------------------
// b[n][o] = mconv_b[o] + sum_i mconv_w[o, 512+i] * lang[n, i]
// ---------------------------------------------------------------------------
__global__ void langbias_kernel(const float* __restrict__ lang,
                                const float* __restrict__ mw,
                                const float* __restrict__ mb) {
    int idx = blockIdx.x * 256 + threadIdx.x;
    if (idx >= NND * CHN) return;
    int n = idx / CHN, o = idx - n * CHN;
    const float* wp = mw + o * 812 + 512;
    const float* lp = lang + n * 300;
    float acc = mb[o];
    for (int i = 0; i < 300; i++) acc += wp[i] * lp[i];
    g_b[idx] = acc;
}

// ---------------------------------------------------------------------------
// t[g][n][tap][o] = sum_{i<512} Wg_x[o,i,tap] * b[n][i]
// one thread per (g,tap,o), computes all 20 n. 54 blocks x 256.
// ---------------------------------------------------------------------------
__global__ void tapconst_kernel(const float* __restrict__ rw,
                                const float* __restrict__ uw,
                                const float* __restrict__ ow) {
    __shared__ float bs[NND * CHN];  // 40KB
    int tid = threadIdx.x;
    for (int idx = tid; idx < NND * CHN; idx += 256) bs[idx] = g_b[idx];
    __syncthreads();
    int gidx = blockIdx.x * 256 + tid;       // 3*9*512 = 13824
    int o   = gidx & (CHN - 1);
    int tap = (gidx >> 9) % 9;
    int g   = gidx / (CHN * 9);
    const float* w = (g == 0) ? rw : (g == 1) ? uw : ow;
    const float* wp = w + o * 9216 + tap;    // i-stride 9, i in [0,512) = x-part
    float acc[NND];
#pragma unroll
    for (int n = 0; n < NND; n++) acc[n] = 0.f;
    for (int i = 0; i < CHN; i++) {
        float wv = wp[i * 9];
#pragma unroll
        for (int n = 0; n < NND; n++) acc[n] += wv * bs[n * CHN + i];
    }
#pragma unroll
    for (int n = 0; n < NND; n++)
        g_t[((g * NND + n) * 9 + tap) * CHN + o] = acc[n];
}

// ---------------------------------------------------------------------------
// GEMM: out[o][p] = sum_{i<K} w[o*ldw + i] * in[i*4096 + p]   (V = vis @ W_vis)
// block: 64 o x 128 p, 128 threads, thread: 8o x 8p (p strided by 16)
// ---------------------------------------------------------------------------
__global__ __launch_bounds__(128) void gemm_kernel(
    const float* __restrict__ in, const float* __restrict__ w,
    int ldw, int K, float* __restrict__ out) {
    __shared__ float xs[8 * 128];
    __shared__ float wsm[8 * 65];
    int pB  = blockIdx.x * 128;
    int coB = blockIdx.y * 64;
    int tid = threadIdx.x;
    int pxg = tid & 15, cog = tid >> 4;
    float acc[8][8];
#pragma unroll
    for (int a = 0; a < 8; a++)
#pragma unroll
        for (int b = 0; b < 8; b++) acc[a][b] = 0.f;

    for (int kb = 0; kb < K; kb += 8) {
        __syncthreads();
        for (int idx = tid; idx < 1024; idx += 128) {
            int i = idx >> 7, p = idx & 127;
            xs[idx] = in[(kb + i) * HW + pB + p];
        }
        for (int idx = tid; idx < 512; idx += 128) {
            int co = idx >> 3, i = idx & 7;
            wsm[i * 65 + co] = w[(coB + co) * ldw + kb + i];
        }
        __syncthreads();
#pragma unroll
        for (int i = 0; i < 8; i++) {
            float xv[8], wv[8];
#pragma unroll
            for (int v = 0; v < 8; v++) xv[v] = xs[i * 128 + pxg + 16 * v];
#pragma unroll
            for (int u = 0; u < 8; u++) wv[u] = wsm[i * 65 + u * 8 + cog];
#pragma unroll
            for (int u = 0; u < 8; u++)
#pragma unroll
                for (int v = 0; v < 8; v++)
                    acc[u][v] = fmaf(wv[u], xv[v], acc[u][v]);
        }
    }
#pragma unroll
    for (int u = 0; u < 8; u++) {
        float* op = out + (coB + u * 8 + cog) * HW + pB + pxg;
#pragma unroll
        for (int v = 0; v < 8; v++) op[16 * v] = acc[u][v];
    }
}

// ---------------------------------------------------------------------------
// Direct 3x3 conv, pad=1, 512ch -> 512ch over 64x64, fp32.
// weights: wbase[(o)*9216 + (w_coff + i)*9 + ky*3 + kx], i in [0,512)
// block: 64 cout x (8 rows x 16 cols), 128 threads, thread: 8co x 8px.
// flag_n >= 0 : skip entirely if g_childcount[flag_n] == 0  (leaf skip)
// ---------------------------------------------------------------------------
__global__ __launch_bounds__(128) void conv3x3_kernel(
    const float* __restrict__ in, const float* __restrict__ wbase,
    int w_coff, float* __restrict__ out, int flag_n) {
    if (flag_n >= 0 && g_childcount[flag_n] == 0) return;

    __shared__ float xs[8 * 10 * 21];   // 8 ci x 10 rows x (18 cols, pitch 21)
    __shared__ float wsm[8 * 9 * 65];   // [ci][tap][co], co pitch 65

    int sp  = blockIdx.x;               // 32 spatial tiles
    int coB = blockIdx.y * 64;
    int ty = sp >> 2, tx = sp & 3;
    int y0 = ty * 8, x0 = tx * 16;

    int tid = threadIdx.x;
    int pxg = tid & 15;
    int cog = tid >> 4;                 // 0..7
    int r   = pxg >> 1;                 // 0..7 row within tile
    int chf = (pxg & 1) * 8;            // col half: 0 or 8

    float acc[8][8];
#pragma unroll
    for (int a = 0; a < 8; a++)
#pragma unroll
        for (int b = 0; b < 8; b++) acc[a][b] = 0.f;

    for (int cb = 0; cb < CHN; cb += 8) {
        __syncthreads();
        // input tile: 8 ci x 10 x 18 with zero halo
        for (int idx = tid; idx < 8 * 10 * 18; idx += 128) {
            int ci  = idx / 180;
            int rem = idx - ci * 180;
            int ry  = rem / 18;
            int rx  = rem - ry * 18;
            int gy = y0 + ry - 1, gx = x0 + rx - 1;
            float v = 0.f;
            if (gy >= 0 && gy < HH && gx >= 0 && gx < WW)
                v = in[(cb + ci) * HW + gy * WW + gx];
            xs[(ci * 10 + ry) * 21 + rx] = v;
        }
        // weights: 64 co x (8 ci x 9 taps), coalesced 72-float runs per co
        for (int idx = tid; idx < 64 * 72; idx += 128) {
            int co  = idx / 72;
            int t72 = idx - co * 72;    // = ci*9 + tap
            wsm[t72 * 65 + co] =
                wbase[(coB + co) * 9216 + (w_coff + cb) * 9 + t72];
        }
        __syncthreads();
#pragma unroll 1
        for (int ci = 0; ci < 8; ci++) {
#pragma unroll
            for (int ky = 0; ky < 3; ky++) {
                float xr[10];
#pragma unroll
                for (int j = 0; j < 10; j++)
                    xr[j] = xs[(ci * 10 + r + ky) * 21 + chf + j];
#pragma unroll
                for (int kx = 0; kx < 3; kx++) {
                    float wv[8];
#pragma unroll
                    for (int u = 0; u < 8; u++)
                        wv[u] = wsm[(ci * 9 + ky * 3 + kx) * 65 + u * 8 + cog];
#pragma unroll
                    for (int u = 0; u < 8; u++)
#pragma unroll
                        for (int v = 0; v < 8; v++)
                            acc[u][v] = fmaf(wv[u], xr[v + kx], acc[u][v]);
                }
            }
        }
    }
    int py = y0 + r, pxc = x0 + chf;
#pragma unroll
    for (int u = 0; u < 8; u++) {
        float4* op = reinterpret_cast<float4*>(
            out + (coB + u * 8 + cog) * HW + py * WW + pxc);
        op[0] = make_float4(acc[u][0], acc[u][1], acc[u][2], acc[u][3]);
        op[1] = make_float4(acc[u][4], acc[u][5], acc[u][6], acc[u][7]);
    }
}

// ---------------------------------------------------------------------------
// gather: for node n with children:
//   cs = sum_k h[k];  rh = sum_k sigmoid(Gr + cr_n(pix) + reset_b + R[k]) * h[k]
// ---------------------------------------------------------------------------
__global__ void gather_kernel(int n, const float* __restrict__ reset_b) {
    int cnt = g_childcount[n];
    if (cnt == 0) return;
    int e = blockIdx.x * 256 + threadIdx.x;
    int c = e >> 12;
    int p = e & (HW - 1);
    int y = p >> 6, x = p & 63;
    const float* t = g_t + (0 * NND + n) * 9 * CHN;
    int ky0 = (y == 0), ky1 = 2 - (y == HH - 1);
    int kx0 = (x == 0), kx1 = 2 - (x == WW - 1);
    float cr = 0.f;
    for (int ky = ky0; ky <= ky1; ky++)
        for (int kx = kx0; kx <= kx1; kx++)
            cr += t[(ky * 3 + kx) * CHN + c];
    float base = g_buf[1 * CHW + e] + reset_b[c] + cr;  // Gr
    float cs = 0.f, rh = 0.f;
    for (int j = 0; j < cnt; j++) {
        int k = g_child[n * NND + j];
        float hv = g_buf[(8 + k) * CHW + e];
        float rr = sigm(base + g_buf[(28 + k) * CHW + e]);
        cs += hv;
        rh += rr * hv;
    }
    g_buf[4 * CHW + e] = cs;   // cs
    g_buf[5 * CHW + e] = rh;   // rh
}

// ---------------------------------------------------------------------------
// combine: h[n] = (1-z)*tanh(Go + co_n + output_b + O) + z*cs
//          z    = sigmoid(Gu + cu_n + update_b + U)
// leaves: U = O = cs = 0
// ---------------------------------------------------------------------------
__global__ void combine_kernel(int n, const float* __restrict__ update_b,
                               const float* __restrict__ output_b,
                               float* __restrict__ dst) {
    int e = blockIdx.x * 256 + threadIdx.x;
    int c = e >> 12;
    int p = e & (HW - 1);
    int y = p >> 6, x = p & 63;
    bool haskids = g_childcount[n] > 0;
    const float* tu = g_t + (1 * NND + n) * 9 * CHN;
    const float* to = g_t + (2 * NND + n) * 9 * CHN;
    int ky0 = (y == 0), ky1 = 2 - (y == HH - 1);
    int kx0 = (x == 0), kx1 = 2 - (x == WW - 1);
    float cu = 0.f, co = 0.f;
    for (int ky = ky0; ky <= ky1; ky++)
        for (int kx = kx0; kx <= kx1; kx++) {
            int oidx = (ky * 3 + kx) * CHN + c;
            cu += tu[oidx];
            co += to[oidx];
        }
    float uacc = haskids ? g_buf[6 * CHW + e] : 0.f;
    float oacc = haskids ? g_buf[7 * CHW + e] : 0.f;
    float cs   = haskids ? g_buf[4 * CHW + e] : 0.f;
    float z  = sigm(g_buf[2 * CHW + e] + update_b[c] + cu + uacc);
    float ri = tanhf(g_buf[3 * CHW + e] + output_b[c] + co + oacc);
    dst[e] = (1.f - z) * ri + z * cs;
}

// ---------------------------------------------------------------------------
extern "C" void kernel_launch(void* const* d_in, const int* in_sizes, int n_in,
                              void* d_out, int out_size) {
    const float* vis  = (const float*)d_in[0];
    const float* lang = (const float*)d_in[1];
    const int*   adj  = (const int*)d_in[2];
    const float* mw   = (const float*)d_in[3];
    const float* mb   = (const float*)d_in[4];
    const float* rw   = (const float*)d_in[5];
    const float* rb   = (const float*)d_in[6];
    const float* uw   = (const float*)d_in[7];
    const float* ub   = (const float*)d_in[8];
    const float* ow   = (const float*)d_in[9];
    const float* ob   = (const float*)d_in[10];
    float* out = (float*)d_out;

    float* buf = nullptr;
    cudaGetSymbolAddress((void**)&buf, g_buf);

    dim3 cgrid(32, 8);

    prep_kernel<<<1, 32>>>(adj);
    langbias_kernel<<<40, 256>>>(lang, mw, mb);
    tapconst_kernel<<<54, 256>>>(rw, uw, ow);

    // V = conv1x1(vis, mconv_w[:, :512])   (bias folded into b_n)
    gemm_kernel<<<cgrid, 128>>>(vis, mw, 812, 512, buf);

    // shared convs of V with each gate's x-part weights
    conv3x3_kernel<<<cgrid, 128>>>(buf, rw, 0, buf + 1 * CHW, -1);  // Gr
    conv3x3_kernel<<<cgrid, 128>>>(buf, uw, 0, buf + 2 * CHW, -1);  // Gu
    conv3x3_kernel<<<cgrid, 128>>>(buf, ow, 0, buf + 3 * CHW, -1);  // Go

    // nodes in decreasing index = valid topological order (parent(i) < i)
    for (int n = NND - 1; n >= 0; n--) {
        gather_kernel<<<8192, 256>>>(n, rb);
        // U = conv3x3(cs, Wu_h), O = conv3x3(rh, Wo_h)  (skipped for leaves)
        conv3x3_kernel<<<cgrid, 128>>>(buf + 4 * CHW, uw, 512, buf + 6 * CHW, n);
        conv3x3_kernel<<<cgrid, 128>>>(buf + 5 * CHW, ow, 512, buf + 7 * CHW, n);
        combine_kernel<<<8192, 256>>>(n, ub, ob,
                                      (n == 0) ? out : buf + (8 + n) * CHW);
        if (n > 0)  // R[n] = conv3x3(h[n], Wr_h) for the parent's reset gates
            conv3x3_kernel<<<cgrid, 128>>>(buf + (8 + n) * CHW, rw, 512,
                                           buf + (28 + n) * CHW, -1);
    }
}

// round 7
// speedup vs baseline: 3.1280x; 3.1280x over previous
#include <cuda_runtime.h>
#include <cuda_bf16.h>
#include <cstdio>
#include <cstdint>

#define NND 20
#define CHN 512
#define HH  64
#define WW  64
#define HW  4096
#define CHW 2097152   // 512*64*64

// Big scratch: [V:1][Gr,Gu,Go:3][cs:1][rh:1][U:1][O:1][h:20][R:20] = 48 planes
__device__ float g_buf[48ll * CHW];
__device__ float g_b[NND * CHN];            // per-node channel bias (lang part + mconv_b)
__device__ float g_t[3 * NND * 9 * CHN];    // per-gate per-node per-tap constant vectors
__device__ int   g_childcount[NND];
__device__ int   g_child[NND * NND];

// bf16 hi/lo weights: [part(6)][split(2)][tap(9)][o(512)][ci(512)]
// parts: 0=reset_x 1=reset_h 2=update_x 3=update_h 4=output_x 5=output_h
__device__ __nv_bfloat16 g_wr[6ll * 2 * 9 * 512 * 512];
// transposed+split inputs: [split(2)][px(4096)][ci(512)] bf16
__device__ __nv_bfloat16 g_tA[2ll * CHW];
__device__ __nv_bfloat16 g_tB[2ll * CHW];
__device__ __nv_bfloat16 g_tC[2ll * CHW];

__device__ __forceinline__ float sigm(float v) { return 1.f / (1.f + expf(-v)); }

// ======================= low-level helpers (sm_100-safe) ====================
__device__ __forceinline__ uint32_t smem_u32(const void* p) {
    uint32_t a;
    asm("{ .reg .u64 t; cvta.to.shared.u64 t, %1; cvt.u32.u64 %0, t; }"
        : "=r"(a) : "l"(p));
    return a;
}
__device__ __forceinline__ void cp16(uint32_t dst, const void* src, uint32_t ssz) {
    asm volatile("cp.async.cg.shared.global [%0], [%1], 16, %2;"
        :: "r"(dst), "l"(src), "r"(ssz) : "memory");
}
__device__ __forceinline__ void ldm4(uint32_t* r, uint32_t addr) {
    asm volatile("ldmatrix.sync.aligned.m8n8.x4.shared.b16 {%0,%1,%2,%3}, [%4];"
        : "=r"(r[0]), "=r"(r[1]), "=r"(r[2]), "=r"(r[3]) : "r"(addr));
}
__device__ __forceinline__ void mma16816(float* c, const uint32_t* a,
                                         uint32_t b0, uint32_t b1) {
    asm volatile(
        "mma.sync.aligned.m16n8k16.row.col.f32.bf16.bf16.f32 "
        "{%0,%1,%2,%3}, {%4,%5,%6,%7}, {%8,%9}, {%0,%1,%2,%3};"
        : "+f"(c[0]), "+f"(c[1]), "+f"(c[2]), "+f"(c[3])
        : "r"(a[0]), "r"(a[1]), "r"(a[2]), "r"(a[3]), "r"(b0), "r"(b1));
}
#define SWZ(off) ((off) ^ (((off) >> 3) & 0x70))

// ---------------------------------------------------------------------------
// Tree prep
// ---------------------------------------------------------------------------
__global__ void prep_kernel(const int* __restrict__ adj) {
    int n = threadIdx.x;
    if (n < NND) {
        int cnt = 0;
        for (int k = 0; k < NND; k++)
            if (adj[n * NND + k] != 0) g_child[n * NND + cnt++] = k;
        g_childcount[n] = cnt;
    }
}

// ---------------------------------------------------------------------------
// b[n][o] = mconv_b[o] + sum_i mconv_w[o, 512+i] * lang[n, i]
// ---------------------------------------------------------------------------
__global__ void langbias_kernel(const float* __restrict__ lang,
                                const float* __restrict__ mw,
                                const float* __restrict__ mb) {
    int idx = blockIdx.x * 256 + threadIdx.x;
    if (idx >= NND * CHN) return;
    int n = idx / CHN, o = idx - n * CHN;
    const float* wp = mw + o * 812 + 512;
    const float* lp = lang + n * 300;
    float acc = mb[o];
    for (int i = 0; i < 300; i++) acc += wp[i] * lp[i];
    g_b[idx] = acc;
}

// ---------------------------------------------------------------------------
// t[g][n][tap][o] = sum_{i<512} Wg_x[o,i,tap] * b[n][i]
// ---------------------------------------------------------------------------
__global__ void tapconst_kernel(const float* __restrict__ rw,
                                const float* __restrict__ uw,
                                const float* __restrict__ ow) {
    __shared__ float bs[NND * CHN];  // 40KB
    int tid = threadIdx.x;
    for (int idx = tid; idx < NND * CHN; idx += 256) bs[idx] = g_b[idx];
    __syncthreads();
    int gidx = blockIdx.x * 256 + tid;
    int o   = gidx & (CHN - 1);
    int tap = (gidx >> 9) % 9;
    int g   = gidx / (CHN * 9);
    const float* w = (g == 0) ? rw : (g == 1) ? uw : ow;
    const float* wp = w + o * 9216 + tap;
    float acc[NND];
#pragma unroll
    for (int n = 0; n < NND; n++) acc[n] = 0.f;
    for (int i = 0; i < CHN; i++) {
        float wv = wp[i * 9];
#pragma unroll
        for (int n = 0; n < NND; n++) acc[n] += wv * bs[n * CHN + i];
    }
#pragma unroll
    for (int n = 0; n < NND; n++)
        g_t[((g * NND + n) * 9 + tap) * CHN + o] = acc[n];
}

// ---------------------------------------------------------------------------
// Weight hi/lo split + transpose into g_wr[part][split][tap][o][ci]
// ---------------------------------------------------------------------------
__global__ void wprep_kernel(const float* __restrict__ rw,
                             const float* __restrict__ uw,
                             const float* __restrict__ ow) {
    int idx = blockIdx.x * 256 + threadIdx.x;
    if (idx >= 6 * 9 * 512 * 512) return;
    int ci = idx & 511;
    int t  = idx >> 9;
    int o  = t & 511; t >>= 9;
    int tap = t % 9;
    int part = t / 9;
    const float* w = (part < 2) ? rw : (part < 4) ? uw : ow;
    int coff = (part & 1) << 9;
    float v = w[(size_t)o * 9216 + (size_t)(coff + ci) * 9 + tap];
    __nv_bfloat16 h = __float2bfloat16(v);
    __nv_bfloat16 l = __float2bfloat16(v - __bfloat162float(h));
    size_t base = ((((size_t)(part * 2) * 9 + tap) * 512 + o) << 9) + ci;
    g_wr[base] = h;
    g_wr[base + (size_t)9 * 512 * 512] = l;  // split=1 stride
}

// ---------------------------------------------------------------------------
// Input transpose + hi/lo split: src[ci][px] fp32 -> dst[split][px][ci] bf16
// ---------------------------------------------------------------------------
__global__ void split_t_kernel(const float* __restrict__ src,
                               __nv_bfloat16* __restrict__ dst, int flag_n) {
    if (flag_n >= 0 && g_childcount[flag_n] == 0) return;
    __shared__ float tile[32][33];
    int tx = threadIdx.x & 31, ty = threadIdx.x >> 5;   // 256 threads
    int p0 = blockIdx.x << 5, ci0 = blockIdx.y << 5;
#pragma unroll
    for (int r = 0; r < 4; r++)
        tile[ty + r * 8][tx] = src[(size_t)(ci0 + ty + r * 8) * HW + p0 + tx];
    __syncthreads();
#pragma unroll
    for (int r = 0; r < 4; r++) {
        int p = p0 + ty + r * 8, ci = ci0 + tx;
        float v = tile[tx][ty + r * 8];
        __nv_bfloat16 h = __float2bfloat16(v);
        float lof = v - __bfloat162float(h);
        dst[(size_t)p * 512 + ci] = h;
        dst[(size_t)CHW + (size_t)p * 512 + ci] = __float2bfloat16(lof);
    }
}

// ---------------------------------------------------------------------------
// GEMM: V = vis @ W_vis  (1x1 conv), fp32 (219us, leave as-is)
// ---------------------------------------------------------------------------
__global__ __launch_bounds__(128) void gemm_kernel(
    const float* __restrict__ in, const float* __restrict__ w,
    int ldw, int K, float* __restrict__ out) {
    __shared__ float xs[8 * 128];
    __shared__ float wsm[8 * 65];
    int pB  = blockIdx.x * 128;
    int coB = blockIdx.y * 64;
    int tid = threadIdx.x;
    int pxg = tid & 15, cog = tid >> 4;
    float acc[8][8];
#pragma unroll
    for (int a = 0; a < 8; a++)
#pragma unroll
        for (int b = 0; b < 8; b++) acc[a][b] = 0.f;

    for (int kb = 0; kb < K; kb += 8) {
        __syncthreads();
        for (int idx = tid; idx < 1024; idx += 128) {
            int i = idx >> 7, p = idx & 127;
            xs[idx] = in[(kb + i) * HW + pB + p];
        }
        for (int idx = tid; idx < 512; idx += 128) {
            int co = idx >> 3, i = idx & 7;
            wsm[i * 65 + co] = w[(coB + co) * ldw + kb + i];
        }
        __syncthreads();
#pragma unroll
        for (int i = 0; i < 8; i++) {
            float xv[8], wv[8];
#pragma unroll
            for (int v = 0; v < 8; v++) xv[v] = xs[i * 128 + pxg + 16 * v];
#pragma unroll
            for (int u = 0; u < 8; u++) wv[u] = wsm[i * 65 + u * 8 + cog];
#pragma unroll
            for (int u = 0; u < 8; u++)
#pragma unroll
                for (int v = 0; v < 8; v++)
                    acc[u][v] = fmaf(wv[u], xv[v], acc[u][v]);
        }
    }
#pragma unroll
    for (int u = 0; u < 8; u++) {
        float* op = out + (coB + u * 8 + cog) * HW + pB + pxg;
#pragma unroll
        for (int v = 0; v < 8; v++) op[16 * v] = acc[u][v];
    }
}

// ---------------------------------------------------------------------------
// mma.sync implicit-GEMM 3x3 conv (bf16 3-split, fp32 accum in registers)
// tin: [split][px][ci] bf16.  out[co][px] fp32 (no bias).
// CTA: 256 thr = 8 warps (2 m x 4 n). Tile 128 co x 128 px (2 image rows).
// Stage: K=64. 216 stages = 3 split-terms x 9 taps x 8 ci-blocks.
// ---------------------------------------------------------------------------
#define CONV_SMEM 65536   // 2 x (A 16KB + B 16KB)

__device__ __forceinline__ void conv_issue_stage(
    int s, int bsel, uint32_t sA, int tid, int yB, int coB,
    const __nv_bfloat16* wbase, const __nv_bfloat16* tin) {
    int split3 = s / 72;
    int t8 = s - split3 * 72;
    int tap = t8 >> 3;
    int cb  = (t8 & 7) << 6;
    int wsplit = (split3 == 1) ? 1 : 0;
    int xsplit = (split3 == 2) ? 1 : 0;
    int ky = tap / 3, kx = tap - ky * 3;

    const __nv_bfloat16* wsrc =
        wbase + ((size_t)wsplit * 9 * 512 * 512) +
        (((size_t)tap * 512 + coB) << 9) + cb;
    const __nv_bfloat16* xsrc = tin + (size_t)xsplit * CHW + cb;
    uint32_t Ab = sA + bsel * 32768;
    uint32_t Bb = Ab + 16384;
    // A: 128 co rows x 64 ci (16KB), 1024 x 16B
#pragma unroll
    for (int it = 0; it < 4; it++) {
        int i = tid + it * 256;
        int o = i >> 3, q = i & 7;
        int off = o * 128 + q * 16;
        cp16(Ab + SWZ(off), wsrc + ((size_t)o << 9) + q * 8, 16u);
    }
    // B: 128 px rows x 64 ci with tap shift + zero halo
#pragma unroll
    for (int it = 0; it < 4; it++) {
        int i = tid + it * 256;
        int j = i >> 3, q = i & 7;
        int jr = j >> 6;
        int sx = (j & 63) + kx - 1;
        int sy = yB + jr + ky - 1;
        bool ok = ((unsigned)sy < 64u) && ((unsigned)sx < 64u);
        int syc = ok ? sy : 0, sxc = ok ? sx : 0;
        int off = j * 128 + q * 16;
        cp16(Bb + SWZ(off),
             xsrc + ((size_t)((syc << 6) + sxc) << 9) + q * 8,
             ok ? 16u : 0u);
    }
    asm volatile("cp.async.commit_group;" ::: "memory");
}

__global__ __launch_bounds__(256)
void conv_mma_kernel(const __nv_bfloat16* __restrict__ tin, int part,
                     float* __restrict__ out, int flag_n) {
    if (flag_n >= 0 && g_childcount[flag_n] == 0) return;
    extern __shared__ char smem[];
    uint32_t sA = smem_u32(smem);
    int tid = threadIdx.x;
    int wid = tid >> 5, lane = tid & 31;
    int yB  = blockIdx.x * 2;
    int pB  = blockIdx.x * 128;
    int coB = blockIdx.y * 128;
    int wm = wid >> 2;           // 0..1 -> co + 64*wm
    int wn = wid & 3;            // 0..3 -> px + 32*wn

    const __nv_bfloat16* wbase = g_wr + (size_t)(part * 2) * 9 * 512 * 512;

    float acc[4][4][4];          // [m-frag][n-frag][c0..c3]
#pragma unroll
    for (int a = 0; a < 4; a++)
#pragma unroll
        for (int b = 0; b < 4; b++)
#pragma unroll
            for (int c = 0; c < 4; c++) acc[a][b][c] = 0.f;

    conv_issue_stage(0, 0, sA, tid, yB, coB, wbase, tin);

    for (int s = 0; s < 216; s++) {
        int bsel = s & 1;
        if (s + 1 < 216) {
            conv_issue_stage(s + 1, bsel ^ 1, sA, tid, yB, coB, wbase, tin);
            asm volatile("cp.async.wait_group 1;" ::: "memory");
        } else {
            asm volatile("cp.async.wait_group 0;" ::: "memory");
        }
        __syncthreads();

        uint32_t Ab = sA + bsel * 32768;
        uint32_t Bb = Ab + 16384;
#pragma unroll
        for (int ks = 0; ks < 4; ks++) {
            uint32_t afr[4][4];
#pragma unroll
            for (int mi = 0; mi < 4; mi++) {
                int row = wm * 64 + mi * 16 + (lane & 15);
                int k16 = ks * 2 + (lane >> 4);
                int off = row * 128 + k16 * 16;
                ldm4(afr[mi], Ab + SWZ(off));
            }
            uint32_t bfr[2][4];
#pragma unroll
            for (int ng = 0; ng < 2; ng++) {
                int n = wn * 32 + ng * 16 + (lane & 7) + ((lane >> 4) << 3);
                int k16 = ks * 2 + ((lane >> 3) & 1);
                int off = n * 128 + k16 * 16;
                ldm4(bfr[ng], Bb + SWZ(off));
            }
            // bfr[ng]: r0=(n0-7,k0-7) r1=(n0-7,k8-15) r2=(n8-15,k0-7) r3=(n8-15,k8-15)
#pragma unroll
            for (int mi = 0; mi < 4; mi++)
#pragma unroll
                for (int ng = 0; ng < 2; ng++) {
                    mma16816(acc[mi][ng * 2 + 0], afr[mi], bfr[ng][0], bfr[ng][1]);
                    mma16816(acc[mi][ng * 2 + 1], afr[mi], bfr[ng][2], bfr[ng][3]);
                }
        }
        __syncthreads();
    }

    // epilogue: D -> out[co*HW + px]
#pragma unroll
    for (int mi = 0; mi < 4; mi++) {
        int row0 = coB + wm * 64 + mi * 16 + (lane >> 2);
#pragma unroll
        for (int nj = 0; nj < 4; nj++) {
            int col = pB + wn * 32 + nj * 8 + (lane & 3) * 2;
            float2 v0 = make_float2(acc[mi][nj][0], acc[mi][nj][1]);
            float2 v1 = make_float2(acc[mi][nj][2], acc[mi][nj][3]);
            *reinterpret_cast<float2*>(out + (size_t)row0 * HW + col) = v0;
            *reinterpret_cast<float2*>(out + (size_t)(row0 + 8) * HW + col) = v1;
        }
    }
}

// ---------------------------------------------------------------------------
// gather: cs = sum h[k]; rh = sum sigmoid(Gr + cr_n + reset_b + R[k]) * h[k]
// ---------------------------------------------------------------------------
__global__ void gather_kernel(int n, const float* __restrict__ reset_b) {
    int cnt = g_childcount[n];
    if (cnt == 0) return;
    int e = blockIdx.x * 256 + threadIdx.x;
    int c = e >> 12;
    int p = e & (HW - 1);
    int y = p >> 6, x = p & 63;
    const float* t = g_t + (0 * NND + n) * 9 * CHN;
    int ky0 = (y == 0), ky1 = 2 - (y == HH - 1);
    int kx0 = (x == 0), kx1 = 2 - (x == WW - 1);
    float cr = 0.f;
    for (int ky = ky0; ky <= ky1; ky++)
        for (int kx = kx0; kx <= kx1; kx++)
            cr += t[(ky * 3 + kx) * CHN + c];
    float base = g_buf[1 * CHW + e] + reset_b[c] + cr;
    float cs = 0.f, rh = 0.f;
    for (int j = 0; j < cnt; j++) {
        int k = g_child[n * NND + j];
        float hv = g_buf[(8 + k) * CHW + e];
        float rr = sigm(base + g_buf[(28 + k) * CHW + e]);
        cs += hv;
        rh += rr * hv;
    }
    g_buf[4 * CHW + e] = cs;
    g_buf[5 * CHW + e] = rh;
}

// ---------------------------------------------------------------------------
// combine: h[n] = (1-z)*tanh(Go + co_n + output_b + O) + z*cs
// ---------------------------------------------------------------------------
__global__ void combine_kernel(int n, const float* __restrict__ update_b,
                               const float* __restrict__ output_b,
                               float* __restrict__ dst) {
    int e = blockIdx.x * 256 + threadIdx.x;
    int c = e >> 12;
    int p = e & (HW - 1);
    int y = p >> 6, x = p & 63;
    bool haskids = g_childcount[n] > 0;
    const float* tu = g_t + (1 * NND + n) * 9 * CHN;
    const float* to = g_t + (2 * NND + n) * 9 * CHN;
    int ky0 = (y == 0), ky1 = 2 - (y == HH - 1);
    int kx0 = (x == 0), kx1 = 2 - (x == WW - 1);
    float cu = 0.f, co = 0.f;
    for (int ky = ky0; ky <= ky1; ky++)
        for (int kx = kx0; kx <= kx1; kx++) {
            int oidx = (ky * 3 + kx) * CHN + c;
            cu += tu[oidx];
            co += to[oidx];
        }
    float uacc = haskids ? g_buf[6 * CHW + e] : 0.f;
    float oacc = haskids ? g_buf[7 * CHW + e] : 0.f;
    float cs   = haskids ? g_buf[4 * CHW + e] : 0.f;
    float z  = sigm(g_buf[2 * CHW + e] + update_b[c] + cu + uacc);
    float ri = tanhf(g_buf[3 * CHW + e] + output_b[c] + co + oacc);
    dst[e] = (1.f - z) * ri + z * cs;
}

// ---------------------------------------------------------------------------
extern "C" void kernel_launch(void* const* d_in, const int* in_sizes, int n_in,
                              void* d_out, int out_size) {
    const float* vis  = (const float*)d_in[0];
    const float* lang = (const float*)d_in[1];
    const int*   adj  = (const int*)d_in[2];
    const float* mw   = (const float*)d_in[3];
    const float* mb   = (const float*)d_in[4];
    const float* rw   = (const float*)d_in[5];
    const float* rb   = (const float*)d_in[6];
    const float* uw   = (const float*)d_in[7];
    const float* ub   = (const float*)d_in[8];
    const float* ow   = (const float*)d_in[9];
    const float* ob   = (const float*)d_in[10];
    float* out = (float*)d_out;

    float* buf = nullptr;
    cudaGetSymbolAddress((void**)&buf, g_buf);
    __nv_bfloat16 *tA = nullptr, *tB = nullptr, *tC = nullptr;
    cudaGetSymbolAddress((void**)&tA, g_tA);
    cudaGetSymbolAddress((void**)&tB, g_tB);
    cudaGetSymbolAddress((void**)&tC, g_tC);

    static bool attr_done = false;
    if (!attr_done) {
        cudaFuncSetAttribute(conv_mma_kernel,
                             cudaFuncAttributeMaxDynamicSharedMemorySize, CONV_SMEM);
        attr_done = true;
    }

    dim3 ggrid(32, 8);       // gemm
    dim3 mgrid(32, 4);       // conv_mma: 32 row-pairs x 4 co-blocks
    dim3 sgrid(128, 16);     // split_t

    prep_kernel<<<1, 32>>>(adj);
    langbias_kernel<<<40, 256>>>(lang, mw, mb);
    tapconst_kernel<<<54, 256>>>(rw, uw, ow);
    wprep_kernel<<<(6 * 9 * 512 * 512 + 255) / 256, 256>>>(rw, uw, ow);

    // V = conv1x1(vis, mconv_w[:, :512])  (bias folded into b_n)
    gemm_kernel<<<ggrid, 128>>>(vis, mw, 812, 512, buf);

    // shared convs of V (x-part weights of the 3 gates)
    split_t_kernel<<<sgrid, 256>>>(buf, tA, -1);
    conv_mma_kernel<<<mgrid, 256, CONV_SMEM>>>(tA, 0, buf + 1 * CHW, -1);  // Gr
    conv_mma_kernel<<<mgrid, 256, CONV_SMEM>>>(tA, 2, buf + 2 * CHW, -1);  // Gu
    conv_mma_kernel<<<mgrid, 256, CONV_SMEM>>>(tA, 4, buf + 3 * CHW, -1);  // Go

    // nodes in decreasing index = valid topological order (parent(i) < i)
    for (int n = NND - 1; n >= 0; n--) {
        gather_kernel<<<8192, 256>>>(n, rb);
        split_t_kernel<<<sgrid, 256>>>(buf + 4 * CHW, tA, n);  // cs
        split_t_kernel<<<sgrid, 256>>>(buf + 5 * CHW, tB, n);  // rh
        conv_mma_kernel<<<mgrid, 256, CONV_SMEM>>>(tA, 3, buf + 6 * CHW, n);  // U
        conv_mma_kernel<<<mgrid, 256, CONV_SMEM>>>(tB, 5, buf + 7 * CHW, n);  // O
        combine_kernel<<<8192, 256>>>(n, ub, ob,
                                      (n == 0) ? out : buf + (8 + n) * CHW);
        if (n > 0) {  // R[n] = conv3x3(h[n], Wr_h)
            split_t_kernel<<<sgrid, 256>>>(buf + (8 + n) * CHW, tC, -1);
            conv_mma_kernel<<<mgrid, 256, CONV_SMEM>>>(tC, 1, buf + (28 + n) * CHW, -1);
        }
    }
}

// round 8
// speedup vs baseline: 3.1425x; 1.0046x over previous
#include <cuda_runtime.h>
#include <cuda_bf16.h>
#include <cstdio>
#include <cstdint>

#define NND 20
#define CHN 512
#define HH  64
#define WW  64
#define HW  4096
#define CHW 2097152   // 512*64*64

// Big scratch: [V:1][Gr,Gu,Go:3][cs:1][rh:1][U:1][O:1][h:20][R:20] = 48 planes
__device__ float g_buf[48ll * CHW];
__device__ float g_b[NND * CHN];            // per-node channel bias (lang part + mconv_b)
__device__ float g_t[3 * NND * 9 * CHN];    // per-gate per-node per-tap constant vectors
__device__ int   g_childcount[NND];
__device__ int   g_child[NND * NND];

// bf16 hi/lo weights: [part(6)][split(2)][tap(9)][o(512)][ci(512)]
// parts: 0=reset_x 1=reset_h 2=update_x 3=update_h 4=output_x 5=output_h
__device__ __nv_bfloat16 g_wr[6ll * 2 * 9 * 512 * 512];
// transposed+split inputs: [split(2)][px(4096)][ci(512)] bf16
__device__ __nv_bfloat16 g_tA[2ll * CHW];
__device__ __nv_bfloat16 g_tB[2ll * CHW];
__device__ __nv_bfloat16 g_tC[2ll * CHW];

__device__ __forceinline__ float sigm(float v) { return 1.f / (1.f + expf(-v)); }

// ======================= low-level helpers (sm_100-safe) ====================
__device__ __forceinline__ uint32_t smem_u32(const void* p) {
    uint32_t a;
    asm("{ .reg .u64 t; cvta.to.shared.u64 t, %1; cvt.u32.u64 %0, t; }"
        : "=r"(a) : "l"(p));
    return a;
}
__device__ __forceinline__ void cp16(uint32_t dst, const void* src, uint32_t ssz) {
    asm volatile("cp.async.cg.shared.global [%0], [%1], 16, %2;"
        :: "r"(dst), "l"(src), "r"(ssz) : "memory");
}
__device__ __forceinline__ void ldm4(uint32_t* r, uint32_t addr) {
    asm volatile("ldmatrix.sync.aligned.m8n8.x4.shared.b16 {%0,%1,%2,%3}, [%4];"
        : "=r"(r[0]), "=r"(r[1]), "=r"(r[2]), "=r"(r[3]) : "r"(addr));
}
__device__ __forceinline__ void mma16816(float* c, const uint32_t* a,
                                         uint32_t b0, uint32_t b1) {
    asm volatile(
        "mma.sync.aligned.m16n8k16.row.col.f32.bf16.bf16.f32 "
        "{%0,%1,%2,%3}, {%4,%5,%6,%7}, {%8,%9}, {%0,%1,%2,%3};"
        : "+f"(c[0]), "+f"(c[1]), "+f"(c[2]), "+f"(c[3])
        : "r"(a[0]), "r"(a[1]), "r"(a[2]), "r"(a[3]), "r"(b0), "r"(b1));
}
#define SWZ(off) ((off) ^ (((off) >> 3) & 0x70))

// ---------------------------------------------------------------------------
// Tree prep
// ---------------------------------------------------------------------------
__global__ void prep_kernel(const int* __restrict__ adj) {
    int n = threadIdx.x;
    if (n < NND) {
        int cnt = 0;
        for (int k = 0; k < NND; k++)
            if (adj[n * NND + k] != 0) g_child[n * NND + cnt++] = k;
        g_childcount[n] = cnt;
    }
}

// ---------------------------------------------------------------------------
// b[n][o] = mconv_b[o] + sum_i mconv_w[o, 512+i] * lang[n, i]
// ---------------------------------------------------------------------------
__global__ void langbias_kernel(const float* __restrict__ lang,
                                const float* __restrict__ mw,
                                const float* __restrict__ mb) {
    int idx = blockIdx.x * 256 + threadIdx.x;
    if (idx >= NND * CHN) return;
    int n = idx / CHN, o = idx - n * CHN;
    const float* wp = mw + o * 812 + 512;
    const float* lp = lang + n * 300;
    float acc = mb[o];
    for (int i = 0; i < 300; i++) acc += wp[i] * lp[i];
    g_b[idx] = acc;
}

// ---------------------------------------------------------------------------
// t[g][n][tap][o] = sum_{i<512} Wg_x[o,i,tap] * b[n][i]
// ---------------------------------------------------------------------------
__global__ void tapconst_kernel(const float* __restrict__ rw,
                                const float* __restrict__ uw,
                                const float* __restrict__ ow) {
    __shared__ float bs[NND * CHN];  // 40KB
    int tid = threadIdx.x;
    for (int idx = tid; idx < NND * CHN; idx += 256) bs[idx] = g_b[idx];
    __syncthreads();
    int gidx = blockIdx.x * 256 + tid;
    int o   = gidx & (CHN - 1);
    int tap = (gidx >> 9) % 9;
    int g   = gidx / (CHN * 9);
    const float* w = (g == 0) ? rw : (g == 1) ? uw : ow;
    const float* wp = w + o * 9216 + tap;
    float acc[NND];
#pragma unroll
    for (int n = 0; n < NND; n++) acc[n] = 0.f;
    for (int i = 0; i < CHN; i++) {
        float wv = wp[i * 9];
#pragma unroll
        for (int n = 0; n < NND; n++) acc[n] += wv * bs[n * CHN + i];
    }
#pragma unroll
    for (int n = 0; n < NND; n++)
        g_t[((g * NND + n) * 9 + tap) * CHN + o] = acc[n];
}

// ---------------------------------------------------------------------------
// Weight hi/lo split + transpose into g_wr[part][split][tap][o][ci]
// ---------------------------------------------------------------------------
__global__ void wprep_kernel(const float* __restrict__ rw,
                             const float* __restrict__ uw,
                             const float* __restrict__ ow) {
    int idx = blockIdx.x * 256 + threadIdx.x;
    if (idx >= 6 * 9 * 512 * 512) return;
    int ci = idx & 511;
    int t  = idx >> 9;
    int o  = t & 511; t >>= 9;
    int tap = t % 9;
    int part = t / 9;
    const float* w = (part < 2) ? rw : (part < 4) ? uw : ow;
    int coff = (part & 1) << 9;
    float v = w[(size_t)o * 9216 + (size_t)(coff + ci) * 9 + tap];
    __nv_bfloat16 h = __float2bfloat16(v);
    __nv_bfloat16 l = __float2bfloat16(v - __bfloat162float(h));
    size_t base = ((((size_t)(part * 2) * 9 + tap) * 512 + o) << 9) + ci;
    g_wr[base] = h;
    g_wr[base + (size_t)9 * 512 * 512] = l;  // split=1 stride
}

// ---------------------------------------------------------------------------
// Input transpose + hi/lo split: src[ci][px] fp32 -> dst[split][px][ci] bf16
// ---------------------------------------------------------------------------
__device__ __forceinline__ void split_t_body(const float* __restrict__ src,
                                             __nv_bfloat16* __restrict__ dst) {
    __shared__ float tile[32][33];
    int tx = threadIdx.x & 31, ty = threadIdx.x >> 5;   // 256 threads
    int p0 = blockIdx.x << 5, ci0 = blockIdx.y << 5;
#pragma unroll
    for (int r = 0; r < 4; r++)
        tile[ty + r * 8][tx] = src[(size_t)(ci0 + ty + r * 8) * HW + p0 + tx];
    __syncthreads();
#pragma unroll
    for (int r = 0; r < 4; r++) {
        int p = p0 + ty + r * 8, ci = ci0 + tx;
        float v = tile[tx][ty + r * 8];
        __nv_bfloat16 h = __float2bfloat16(v);
        float lof = v - __bfloat162float(h);
        dst[(size_t)p * 512 + ci] = h;
        dst[(size_t)CHW + (size_t)p * 512 + ci] = __float2bfloat16(lof);
    }
}
__global__ void split_t_kernel(const float* __restrict__ src,
                               __nv_bfloat16* __restrict__ dst, int flag_n) {
    if (flag_n >= 0 && g_childcount[flag_n] == 0) return;
    split_t_body(src, dst);
}
// dual: z=0 src0->dst0, z=1 src1->dst1
__global__ void split_t_dual_kernel(const float* __restrict__ src0,
                                    __nv_bfloat16* __restrict__ dst0,
                                    const float* __restrict__ src1,
                                    __nv_bfloat16* __restrict__ dst1,
                                    int flag_n) {
    if (flag_n >= 0 && g_childcount[flag_n] == 0) return;
    if (blockIdx.z == 0) split_t_body(src0, dst0);
    else                 split_t_body(src1, dst1);
}

// ---------------------------------------------------------------------------
// GEMM: V = vis @ W_vis  (1x1 conv), fp32 (219us, leave as-is)
// ---------------------------------------------------------------------------
__global__ __launch_bounds__(128) void gemm_kernel(
    const float* __restrict__ in, const float* __restrict__ w,
    int ldw, int K, float* __restrict__ out) {
    __shared__ float xs[8 * 128];
    __shared__ float wsm[8 * 65];
    int pB  = blockIdx.x * 128;
    int coB = blockIdx.y * 64;
    int tid = threadIdx.x;
    int pxg = tid & 15, cog = tid >> 4;
    float acc[8][8];
#pragma unroll
    for (int a = 0; a < 8; a++)
#pragma unroll
        for (int b = 0; b < 8; b++) acc[a][b] = 0.f;

    for (int kb = 0; kb < K; kb += 8) {
        __syncthreads();
        for (int idx = tid; idx < 1024; idx += 128) {
            int i = idx >> 7, p = idx & 127;
            xs[idx] = in[(kb + i) * HW + pB + p];
        }
        for (int idx = tid; idx < 512; idx += 128) {
            int co = idx >> 3, i = idx & 7;
            wsm[i * 65 + co] = w[(coB + co) * ldw + kb + i];
        }
        __syncthreads();
#pragma unroll
        for (int i = 0; i < 8; i++) {
            float xv[8], wv[8];
#pragma unroll
            for (int v = 0; v < 8; v++) xv[v] = xs[i * 128 + pxg + 16 * v];
#pragma unroll
            for (int u = 0; u < 8; u++) wv[u] = wsm[i * 65 + u * 8 + cog];
#pragma unroll
            for (int u = 0; u < 8; u++)
#pragma unroll
                for (int v = 0; v < 8; v++)
                    acc[u][v] = fmaf(wv[u], xv[v], acc[u][v]);
        }
    }
#pragma unroll
    for (int u = 0; u < 8; u++) {
        float* op = out + (coB + u * 8 + cog) * HW + pB + pxg;
#pragma unroll
        for (int v = 0; v < 8; v++) op[16 * v] = acc[u][v];
    }
}

// ---------------------------------------------------------------------------
// mma.sync implicit-GEMM 3x3 conv (bf16 3-split, fp32 accum in registers)
// tin: [split][px][ci] bf16.  out[co][px] fp32 (no bias).
// CTA: 128 thr = 4 warps (2 m x 2 n). Tile 128 co x 128 px, warp tile 64x64.
// Stage: K=64. 216 stages = 3 split-terms x 9 taps x 8 ci-blocks.
// 3-stage cp.async pipeline, ONE __syncthreads per stage.
// ---------------------------------------------------------------------------
#define CONV_SMEM 98304   // 3 x (A 16KB + B 16KB)

__device__ __forceinline__ void conv_issue_stage(
    int s, uint32_t sA, int tid, int yB, int coB,
    const __nv_bfloat16* wbase, const __nv_bfloat16* tin) {
    int split3 = s / 72;
    int t8 = s - split3 * 72;
    int tap = t8 >> 3;
    int cb  = (t8 & 7) << 6;
    int wsplit = (split3 == 1) ? 1 : 0;
    int xsplit = (split3 == 2) ? 1 : 0;
    int ky = tap / 3, kx = tap - ky * 3;

    const __nv_bfloat16* wsrc =
        wbase + ((size_t)wsplit * 9 * 512 * 512) +
        (((size_t)tap * 512 + coB) << 9) + cb;
    const __nv_bfloat16* xsrc = tin + (size_t)xsplit * CHW + cb;
    int bsel = s % 3;
    uint32_t Ab = sA + bsel * 32768;
    uint32_t Bb = Ab + 16384;
    // A: 128 co rows x 64 ci (16KB), 1024 x 16B
#pragma unroll
    for (int it = 0; it < 8; it++) {
        int i = tid + it * 128;
        int o = i >> 3, q = i & 7;
        int off = o * 128 + q * 16;
        cp16(Ab + SWZ(off), wsrc + ((size_t)o << 9) + q * 8, 16u);
    }
    // B: 128 px rows x 64 ci with tap shift + zero halo
#pragma unroll
    for (int it = 0; it < 8; it++) {
        int i = tid + it * 128;
        int j = i >> 3, q = i & 7;
        int jr = j >> 6;
        int sx = (j & 63) + kx - 1;
        int sy = yB + jr + ky - 1;
        bool ok = ((unsigned)sy < 64u) && ((unsigned)sx < 64u);
        int syc = ok ? sy : 0, sxc = ok ? sx : 0;
        int off = j * 128 + q * 16;
        cp16(Bb + SWZ(off),
             xsrc + ((size_t)((syc << 6) + sxc) << 9) + q * 8,
             ok ? 16u : 0u);
    }
    asm volatile("cp.async.commit_group;" ::: "memory");
}

__device__ __forceinline__ void conv_mma_body(
    const __nv_bfloat16* __restrict__ tin, int part,
    float* __restrict__ out, char* smem) {
    uint32_t sA = smem_u32(smem);
    int tid = threadIdx.x;
    int wid = tid >> 5, lane = tid & 31;
    int yB  = blockIdx.x * 2;
    int pB  = blockIdx.x * 128;
    int coB = blockIdx.y * 128;
    int wm = wid >> 1;           // 0..1 -> co + 64*wm
    int wn = wid & 1;            // 0..1 -> px + 64*wn

    const __nv_bfloat16* wbase = g_wr + (size_t)(part * 2) * 9 * 512 * 512;

    float acc[4][8][4];          // [m-frag 16][n-frag 8][c0..c3]
#pragma unroll
    for (int a = 0; a < 4; a++)
#pragma unroll
        for (int b = 0; b < 8; b++)
#pragma unroll
            for (int c = 0; c < 4; c++) acc[a][b][c] = 0.f;

    conv_issue_stage(0, sA, tid, yB, coB, wbase, tin);
    conv_issue_stage(1, sA, tid, yB, coB, wbase, tin);

    for (int s = 0; s < 216; s++) {
        asm volatile("cp.async.wait_group 1;" ::: "memory");
        __syncthreads();   // stage s ready for all; reads of buf[(s+2)%3] done
        if (s + 2 < 216)
            conv_issue_stage(s + 2, sA, tid, yB, coB, wbase, tin);

        uint32_t Ab = sA + (s % 3) * 32768;
        uint32_t Bb = Ab + 16384;
#pragma unroll
        for (int ks = 0; ks < 4; ks++) {
            uint32_t afr[4][4];
#pragma unroll
            for (int mi = 0; mi < 4; mi++) {
                int row = wm * 64 + mi * 16 + (lane & 15);
                int k16 = ks * 2 + (lane >> 4);
                int off = row * 128 + k16 * 16;
                ldm4(afr[mi], Ab + SWZ(off));
            }
            uint32_t bfr[4][4];
#pragma unroll
            for (int ng = 0; ng < 4; ng++) {
                int n = wn * 64 + ng * 16 + (lane & 7) + ((lane >> 4) << 3);
                int k16 = ks * 2 + ((lane >> 3) & 1);
                int off = n * 128 + k16 * 16;
                ldm4(bfr[ng], Bb + SWZ(off));
            }
#pragma unroll
            for (int mi = 0; mi < 4; mi++)
#pragma unroll
                for (int ng = 0; ng < 4; ng++) {
                    mma16816(acc[mi][ng * 2 + 0], afr[mi], bfr[ng][0], bfr[ng][1]);
                    mma16816(acc[mi][ng * 2 + 1], afr[mi], bfr[ng][2], bfr[ng][3]);
                }
        }
    }

    // epilogue: D -> out[co*HW + px]
#pragma unroll
    for (int mi = 0; mi < 4; mi++) {
        int row0 = coB + wm * 64 + mi * 16 + (lane >> 2);
#pragma unroll
        for (int nj = 0; nj < 8; nj++) {
            int col = pB + wn * 64 + nj * 8 + (lane & 3) * 2;
            float2 v0 = make_float2(acc[mi][nj][0], acc[mi][nj][1]);
            float2 v1 = make_float2(acc[mi][nj][2], acc[mi][nj][3]);
            *reinterpret_cast<float2*>(out + (size_t)row0 * HW + col) = v0;
            *reinterpret_cast<float2*>(out + (size_t)(row0 + 8) * HW + col) = v1;
        }
    }
}

__global__ __launch_bounds__(128)
void conv_mma_kernel(const __nv_bfloat16* __restrict__ tin, int part,
                     float* __restrict__ out, int flag_n) {
    if (flag_n >= 0 && g_childcount[flag_n] == 0) return;
    extern __shared__ char smem[];
    conv_mma_body(tin, part, out, smem);
}

// dual-conv: z=0 -> (tin0, part0, out0), z=1 -> (tin1, part1, out1)
__global__ __launch_bounds__(128)
void conv_mma_dual_kernel(const __nv_bfloat16* __restrict__ tin0, int part0,
                          float* __restrict__ out0,
                          const __nv_bfloat16* __restrict__ tin1, int part1,
                          float* __restrict__ out1, int flag_n) {
    if (flag_n >= 0 && g_childcount[flag_n] == 0) return;
    extern __shared__ char smem[];
    if (blockIdx.z == 0) conv_mma_body(tin0, part0, out0, smem);
    else                 conv_mma_body(tin1, part1, out1, smem);
}

// ---------------------------------------------------------------------------
// gather: cs = sum h[k]; rh = sum sigmoid(Gr + cr_n + reset_b + R[k]) * h[k]
// ---------------------------------------------------------------------------
__global__ void gather_kernel(int n, const float* __restrict__ reset_b) {
    int cnt = g_childcount[n];
    if (cnt == 0) return;
    int e = blockIdx.x * 256 + threadIdx.x;
    int c = e >> 12;
    int p = e & (HW - 1);
    int y = p >> 6, x = p & 63;
    const float* t = g_t + (0 * NND + n) * 9 * CHN;
    int ky0 = (y == 0), ky1 = 2 - (y == HH - 1);
    int kx0 = (x == 0), kx1 = 2 - (x == WW - 1);
    float cr = 0.f;
    for (int ky = ky0; ky <= ky1; ky++)
        for (int kx = kx0; kx <= kx1; kx++)
            cr += t[(ky * 3 + kx) * CHN + c];
    float base = g_buf[1 * CHW + e] + reset_b[c] + cr;
    float cs = 0.f, rh = 0.f;
    for (int j = 0; j < cnt; j++) {
        int k = g_child[n * NND + j];
        float hv = g_buf[(8 + k) * CHW + e];
        float rr = sigm(base + g_buf[(28 + k) * CHW + e]);
        cs += hv;
        rh += rr * hv;
    }
    g_buf[4 * CHW + e] = cs;
    g_buf[5 * CHW + e] = rh;
}

// ---------------------------------------------------------------------------
// combine: h[n] = (1-z)*tanh(Go + co_n + output_b + O) + z*cs
// ---------------------------------------------------------------------------
__global__ void combine_kernel(int n, const float* __restrict__ update_b,
                               const float* __restrict__ output_b,
                               float* __restrict__ dst) {
    int e = blockIdx.x * 256 + threadIdx.x;
    int c = e >> 12;
    int p = e & (HW - 1);
    int y = p >> 6, x = p & 63;
    bool haskids = g_childcount[n] > 0;
    const float* tu = g_t + (1 * NND + n) * 9 * CHN;
    const float* to = g_t + (2 * NND + n) * 9 * CHN;
    int ky0 = (y == 0), ky1 = 2 - (y == HH - 1);
    int kx0 = (x == 0), kx1 = 2 - (x == WW - 1);
    float cu = 0.f, co = 0.f;
    for (int ky = ky0; ky <= ky1; ky++)
        for (int kx = kx0; kx <= kx1; kx++) {
            int oidx = (ky * 3 + kx) * CHN + c;
            cu += tu[oidx];
            co += to[oidx];
        }
    float uacc = haskids ? g_buf[6 * CHW + e] : 0.f;
    float oacc = haskids ? g_buf[7 * CHW + e] : 0.f;
    float cs   = haskids ? g_buf[4 * CHW + e] : 0.f;
    float z  = sigm(g_buf[2 * CHW + e] + update_b[c] + cu + uacc);
    float ri = tanhf(g_buf[3 * CHW + e] + output_b[c] + co + oacc);
    dst[e] = (1.f - z) * ri + z * cs;
}

// ---------------------------------------------------------------------------
extern "C" void kernel_launch(void* const* d_in, const int* in_sizes, int n_in,
                              void* d_out, int out_size) {
    const float* vis  = (const float*)d_in[0];
    const float* lang = (const float*)d_in[1];
    const int*   adj  = (const int*)d_in[2];
    const float* mw   = (const float*)d_in[3];
    const float* mb   = (const float*)d_in[4];
    const float* rw   = (const float*)d_in[5];
    const float* rb   = (const float*)d_in[6];
    const float* uw   = (const float*)d_in[7];
    const float* ub   = (const float*)d_in[8];
    const float* ow   = (const float*)d_in[9];
    const float* ob   = (const float*)d_in[10];
    float* out = (float*)d_out;

    float* buf = nullptr;
    cudaGetSymbolAddress((void**)&buf, g_buf);
    __nv_bfloat16 *tA = nullptr, *tB = nullptr, *tC = nullptr;
    cudaGetSymbolAddress((void**)&tA, g_tA);
    cudaGetSymbolAddress((void**)&tB, g_tB);
    cudaGetSymbolAddress((void**)&tC, g_tC);

    static bool attr_done = false;
    if (!attr_done) {
        cudaFuncSetAttribute(conv_mma_kernel,
                             cudaFuncAttributeMaxDynamicSharedMemorySize, CONV_SMEM);
        cudaFuncSetAttribute(conv_mma_dual_kernel,
                             cudaFuncAttributeMaxDynamicSharedMemorySize, CONV_SMEM);
        attr_done = true;
    }

    dim3 ggrid(32, 8);            // gemm
    dim3 mgrid(32, 4);            // conv: 32 row-pairs x 4 co-blocks
    dim3 mgrid2(32, 4, 2);        // dual conv
    dim3 sgrid(128, 16);          // split_t
    dim3 sgrid2(128, 16, 2);      // dual split_t

    prep_kernel<<<1, 32>>>(adj);
    langbias_kernel<<<40, 256>>>(lang, mw, mb);
    tapconst_kernel<<<54, 256>>>(rw, uw, ow);
    wprep_kernel<<<(6 * 9 * 512 * 512 + 255) / 256, 256>>>(rw, uw, ow);

    // V = conv1x1(vis, mconv_w[:, :512])  (bias folded into b_n)
    gemm_kernel<<<ggrid, 128>>>(vis, mw, 812, 512, buf);

    // shared convs of V (x-part weights of the 3 gates)
    split_t_kernel<<<sgrid, 256>>>(buf, tA, -1);
    conv_mma_kernel<<<mgrid, 128, CONV_SMEM>>>(tA, 0, buf + 1 * CHW, -1);  // Gr
    conv_mma_dual_kernel<<<mgrid2, 128, CONV_SMEM>>>(
        tA, 2, buf + 2 * CHW, tA, 4, buf + 3 * CHW, -1);                   // Gu, Go

    // nodes in decreasing index = valid topological order (parent(i) < i)
    for (int n = NND - 1; n >= 0; n--) {
        gather_kernel<<<8192, 256>>>(n, rb);
        split_t_dual_kernel<<<sgrid2, 256>>>(buf + 4 * CHW, tA,
                                             buf + 5 * CHW, tB, n);  // cs, rh
        conv_mma_dual_kernel<<<mgrid2, 128, CONV_SMEM>>>(
            tA, 3, buf + 6 * CHW, tB, 5, buf + 7 * CHW, n);          // U, O
        combine_kernel<<<8192, 256>>>(n, ub, ob,
                                      (n == 0) ? out : buf + (8 + n) * CHW);
        if (n > 0) {  // R[n] = conv3x3(h[n], Wr_h)
            split_t_kernel<<<sgrid, 256>>>(buf + (8 + n) * CHW, tC, -1);
            conv_mma_kernel<<<mgrid, 128, CONV_SMEM>>>(tC, 1, buf + (28 + n) * CHW, -1);
        }
    }
}